// round 14
// baseline (speedup 1.0000x reference)
#include <cuda_runtime.h>
#include <cuda_fp16.h>
#include <cstdint>
#include <cstddef>

// Problem constants
#define B_   32
#define T_   512
#define E_   300
#define EP_  320              // padded embedding K (mult of 32)
#define H_   1024
#define G4_  4096             // 4*H
#define M_   (B_*T_)          // 16384 token rows
#define NCTA_REC 128

// ---------------- scratch (device globals; no allocation allowed) ----------
__device__ __half   g_x   [(size_t)M_ * EP_];      // embedded inputs (fp16)
__device__ __half   g_wA  [(size_t)G4_ * 2048];    // converted w_ih (dir f)
__device__ __half   g_wB  [(size_t)G4_ * 2048];    // converted w_ih (dir b)
__device__ __half   g_whF [(size_t)G4_ * H_];      // converted w_hh fwd (fp16)
__device__ __half   g_whB [(size_t)G4_ * H_];      // converted w_hh bwd (fp16)
__device__ float    g_xpF [(size_t)M_ * G4_];      // input projection fwd
__device__ float    g_xpB [(size_t)M_ * G4_];      // input projection bwd
__device__ __half   g_out0[(size_t)M_ * 2 * H_];   // layer0 output (fp16)
__device__ __half   g_hF  [B_ * H_];               // sorted-row layout
__device__ __half   g_hB  [B_ * H_];
__device__ int      g_idx [M_];                    // compacted row -> b*T+t
__device__ int      g_Mc;                          // number of active rows
__device__ int      g_perm[B_];                    // sorted row -> orig batch
__device__ int      g_nbt [T_];                    // active batches at step t
__device__ int      g_Tmax;                        // max length
__device__ unsigned g_cnt [16 * 32];               // striped counters (8/dir)
__device__ unsigned g_cntm[2 * 32];                // master counter per dir
__device__ volatile unsigned g_bgen[2 * 32];       // barrier gen per dir

// ---------------- helpers ---------------------------------------------------
__device__ __forceinline__ void mma16(float* c, const uint32_t* a, const uint32_t* b) {
    asm volatile(
        "mma.sync.aligned.m16n8k16.row.col.f32.f16.f16.f32 "
        "{%0,%1,%2,%3},{%4,%5,%6,%7},{%8,%9},{%0,%1,%2,%3};"
        : "+f"(c[0]), "+f"(c[1]), "+f"(c[2]), "+f"(c[3])
        : "r"(a[0]), "r"(a[1]), "r"(a[2]), "r"(a[3]), "r"(b[0]), "r"(b[1]));
}

__device__ __forceinline__ void ldsm4(uint32_t* r, uint32_t addr) {
    asm volatile("ldmatrix.sync.aligned.m8n8.x4.shared.b16 {%0,%1,%2,%3}, [%4];"
        : "=r"(r[0]), "=r"(r[1]), "=r"(r[2]), "=r"(r[3]) : "r"(addr));
}

__device__ __forceinline__ float sigmoidf_(float x) { return 1.f / (1.f + __expf(-x)); }

__device__ __forceinline__ uint32_t s2u(const void* p) {
    uint32_t r;
    asm("{ .reg .u64 t; cvta.to.shared.u64 t, %1; cvt.u32.u64 %0, t; }" : "=r"(r) : "l"(p));
    return r;
}
__device__ __forceinline__ void cp16(void* smem, const void* gmem) {
    asm volatile("cp.async.cg.shared.global [%0], [%1], 16;\n" :: "r"(s2u(smem)), "l"(gmem));
}
__device__ __forceinline__ void cp_commit() { asm volatile("cp.async.commit_group;"); }
template<int N> __device__ __forceinline__ void cp_wait() {
    asm volatile("cp.async.wait_group %0;" :: "n"(N));
}

// Per-direction grid barrier: 64 CTAs per direction, 8 stripes of 8.
// Monotonic epochs: no resets, safe across kernel instances & graph replays.
__device__ __forceinline__ void grid_barrier(int dir, unsigned epoch) {
    __threadfence();
    __syncthreads();
    if (threadIdx.x == 0) {
        unsigned s = (dir * 8 + (blockIdx.x & 7)) * 32;
        unsigned v = atomicAdd(&g_cnt[s], 1u) + 1u;
        if (v == 8u * epoch) {                         // last arrival in stripe
            unsigned a = atomicAdd(&g_cntm[dir * 32], 1u) + 1u;
            if (a == 8u * epoch) {                     // last stripe of this dir
                __threadfence();
                g_bgen[dir * 32] = epoch;
            }
        }
        while (g_bgen[dir * 32] < epoch) { }
    }
    __syncthreads();
}

// ---------------- kernel 0: compacted index + sort + nbt -------------------
__global__ __launch_bounds__(256) void build_idx_kernel(const int* __restrict__ lens)
{
    __shared__ int sl[B_];
    __shared__ int offs[B_];
    int tid = threadIdx.x;
    if (tid < B_) sl[tid] = lens[tid];
    __syncthreads();
    if (tid == 0) {
        int s = 0;
        for (int b = 0; b < B_; b++) { offs[b] = s; s += sl[b]; }
        g_Mc = s;
        int pr[B_];
        for (int i = 0; i < B_; i++) pr[i] = i;
        for (int i = 0; i < B_; i++) {
            int best = i;
            for (int j = i + 1; j < B_; j++)
                if (sl[pr[j]] > sl[pr[best]]) best = j;
            int tmp = pr[i]; pr[i] = pr[best]; pr[best] = tmp;
        }
        int mx = 0;
        for (int i = 0; i < B_; i++) {
            g_perm[i] = pr[i];
            if (sl[i] > mx) mx = sl[i];
        }
        g_Tmax = mx;
    }
    __syncthreads();
    for (int t = tid; t < T_; t += 256) {
        int c = 0;
        for (int b = 0; b < B_; b++) c += (sl[b] > t);
        g_nbt[t] = c;
    }
    for (int b = 0; b < B_; b++) {
        int len = sl[b], o = offs[b];
        for (int t = tid; t < len; t += 256)
            g_idx[o + t] = b * T_ + t;
    }
}

// ---------------- kernel 1: embedding gather (emit fp16, pad to 320) -------
__global__ __launch_bounds__(256) void gather_kernel(
    const int* __restrict__ tok, const float* __restrict__ emb, __half* __restrict__ x)
{
    int i = blockIdx.x * 256 + threadIdx.x;
    if (i >= M_ * EP_) return;
    int bt = i / EP_;
    int e  = i - bt * EP_;
    x[i] = (e < E_) ? __float2half_rn(emb[(size_t)tok[bt] * E_ + e]) : __float2half(0.f);
}

// ---------------- kernel 1b: fp32 -> fp16 convert (with K padding) ---------
__global__ __launch_bounds__(256) void conv_f16_pad(
    const float* __restrict__ src, __half* __restrict__ dst, int N, int K, int Kp)
{
    int i = blockIdx.x * 256 + threadIdx.x;
    if (i >= N * Kp) return;
    int n = i / Kp, k = i - n * Kp;
    dst[i] = (k < K) ? __float2half_rn(src[(size_t)n * K + k]) : __half(0.f);
}

__global__ __launch_bounds__(256) void conv_f16_v4(
    const float4* __restrict__ src, __half2* __restrict__ dst, int n4)
{
    int i = blockIdx.x * 256 + threadIdx.x;
    if (i >= n4) return;
    float4 v = src[i];
    dst[2 * i]     = __floats2half2_rn(v.x, v.y);
    dst[2 * i + 1] = __floats2half2_rn(v.z, v.w);
}

// ---------------- kernel 2: fp16 GEMM over compacted rows ------------------
// 4-stage cp.async ring (prefetch distance 3), tiles 128x128x32.
#define GST 4
#define ASTR 40
#define GEMM_SMEM (2 * GST * 128 * ASTR * 2)
__global__ __launch_bounds__(256, 2) void gemm_f16(
    const __half* __restrict__ A, const __half* __restrict__ Bw,
    const float* __restrict__ bias1, const float* __restrict__ bias2,
    float* __restrict__ C, int Ka)
{
    extern __shared__ char smraw[];
    __half* As = (__half*)smraw;                  // GST * 128 * ASTR
    __half* Bs = As + GST * 128 * ASTR;

    const int tid = threadIdx.x, warp = tid >> 5, lane = tid & 31;
    const int m0 = blockIdx.y * 128, n0 = blockIdx.x * 128;
    const int Mc = g_Mc;
    if (m0 >= Mc) return;
    const int wm = (warp >> 1) * 32, wn = (warp & 1) * 64;
    const __half* Bg = Bw + (size_t)n0 * Ka;

    const __half* Arow[2];
#pragma unroll
    for (int i = 0; i < 2; i++) {
        int glob = m0 + (tid >> 2) + 64 * i;
        int src  = g_idx[glob < Mc ? glob : Mc - 1];
        Arow[i] = A + (size_t)src * Ka + (tid & 3) * 8;
    }

    float acc[2][8][4];
#pragma unroll
    for (int i = 0; i < 2; i++)
#pragma unroll
        for (int j = 0; j < 8; j++)
#pragma unroll
            for (int k = 0; k < 4; k++) acc[i][j][k] = 0.f;

    auto issue = [&](int st, int kc) {
#pragma unroll
        for (int i = 0; i < 2; i++) {
            int row = (tid >> 2) + 64 * i, c8 = (tid & 3) * 8;
            cp16(As + st * 128 * ASTR + row * ASTR + c8, Arow[i] + kc);
            cp16(Bs + st * 128 * ASTR + row * ASTR + c8, Bg + (size_t)row * Ka + kc + c8);
        }
    };

    const int nc = Ka >> 5;
    issue(0, 0);  cp_commit();
    if (nc > 1) issue(1, 32);  cp_commit();
    if (nc > 2) issue(2, 64);  cp_commit();

    const uint32_t Au = s2u(As), Bu = s2u(Bs);
    const int rpA = (lane & 7) + ((lane >> 3) & 1) * 8;
    const int kpA = (lane >> 4) * 8;
    const int rpB = (lane & 7) + (lane >> 4) * 8;
    const int kpB = ((lane >> 3) & 1) * 8;

    for (int c = 0; c < nc; c++) {
        if (c + 2 < nc) cp_wait<2>();
        else if (c + 1 < nc) cp_wait<1>();
        else cp_wait<0>();
        __syncthreads();
        if (c + 3 < nc) { issue((c + 3) % GST, (c + 3) * 32); cp_commit(); }

        const uint32_t ab = Au + (c % GST) * 128 * ASTR * 2;
        const uint32_t bb = Bu + (c % GST) * 128 * ASTR * 2;
#pragma unroll
        for (int kk = 0; kk < 32; kk += 16) {
            uint32_t af[2][4], bf[4][4];
#pragma unroll
            for (int mt = 0; mt < 2; mt++)
                ldsm4(af[mt], ab + ((wm + mt * 16 + rpA) * ASTR + kpA + kk) * 2);
#pragma unroll
            for (int nt4 = 0; nt4 < 4; nt4++)
                ldsm4(bf[nt4], bb + ((wn + nt4 * 16 + rpB) * ASTR + kpB + kk) * 2);
#pragma unroll
            for (int mt = 0; mt < 2; mt++)
#pragma unroll
                for (int nt4 = 0; nt4 < 4; nt4++) {
                    mma16(acc[mt][nt4 * 2],     af[mt], bf[nt4]);
                    mma16(acc[mt][nt4 * 2 + 1], af[mt], bf[nt4] + 2);
                }
        }
    }

    int rg[4]; size_t drow[4]; bool val[4];
#pragma unroll
    for (int mt = 0; mt < 2; mt++) {
        rg[mt * 2]     = m0 + wm + mt * 16 + (lane >> 2);
        rg[mt * 2 + 1] = rg[mt * 2] + 8;
    }
#pragma unroll
    for (int i = 0; i < 4; i++) {
        val[i]  = rg[i] < Mc;
        drow[i] = val[i] ? (size_t)g_idx[rg[i]] * G4_ : 0;
    }
#pragma unroll
    for (int mt = 0; mt < 2; mt++)
#pragma unroll
        for (int nt = 0; nt < 8; nt++) {
            int col = n0 + wn + nt * 8 + 2 * (lane & 3);
            float bv0 = bias1[col] + bias2[col];
            float bv1 = bias1[col + 1] + bias2[col + 1];
            if (val[mt * 2]) {
                C[drow[mt * 2] + col]     = acc[mt][nt][0] + bv0;
                C[drow[mt * 2] + col + 1] = acc[mt][nt][1] + bv1;
            }
            if (val[mt * 2 + 1]) {
                C[drow[mt * 2 + 1] + col]     = acc[mt][nt][2] + bv0;
                C[drow[mt * 2 + 1] + col + 1] = acc[mt][nt][3] + bv1;
            }
        }
}

// ---------------- kernel 3: persistent bi-LSTM layer (fp16, resident W) ----
// 8 warps = 4 k-quarters (k=256) x 2 n-halves (n=32). Gate partials alias the
// h tile. Two phases: quarters 0-1 compute on chunks 0-1 while 2-3 stream.
// h loads at 8-row granularity: nrow8 = ceil(nb/8).
#define HSTRH 1032            // half-stride, mod 64 == 8 -> conflict-free ldsm
#define LSTM_SMEM ((64 + 32) * HSTRH * 2 + 512*4 + 512*4 + T_*4 + 64*4 + 128)
__global__ __launch_bounds__(256) void lstm_layer_kernel(
    const float* __restrict__ xpF, const float* __restrict__ xpB,
    const __half* __restrict__ WhF, const __half* __restrict__ WhB,
    const int* __restrict__ lengths,
    __half* __restrict__ out,             // (B*T) x 2H fp16, or nullptr
    __half* __restrict__ hF, __half* __restrict__ hB)
{
    extern __shared__ char smraw[];
    __half* WH  = (__half*)smraw;                 // [64][HSTRH] resident W
    __half* HT  = WH + 64 * HSTRH;                // [32][HSTRH] h tile
    float*  GSB = (float*)HT;                     // [4][32][64] gate partials (ALIAS)
    float*  CST = (float*)(HT + 32 * HSTRH);      // [512]
    float*  HST = CST + 512;                      // [512]
    int*    NBT = (int*)(HST + 512);              // [T_]
    int*    SLEN = NBT + T_;                      // [32] sorted lengths
    int*    SPRM = SLEN + 32;                     // [32] sorted -> orig batch

    const int tid = threadIdx.x, warp = tid >> 5, lane = tid & 31;
    const int cta = blockIdx.x;
    const int dir = cta >> 6;
    const int j0  = (cta & 63) * 16;
    const float*  xp   = dir ? xpB : xpF;
    const __half* Wh   = dir ? WhB : WhF;
    __half*       hdir = dir ? hB : hF;

    unsigned epoch = g_bgen[dir * 32];

    for (int p = tid; p < 512; p += 256) {
        int b = p >> 4, jl = p & 15;
        CST[p] = 0.f; HST[p] = 0.f;
        hdir[b * H_ + j0 + jl] = __float2half(0.f);
    }
    if (tid < 32) {
        int pb = g_perm[tid];
        SPRM[tid] = pb;
        SLEN[tid] = lengths[pb];
    }
    for (int i = tid; i < T_; i += 256) NBT[i] = g_nbt[i];
    const int Tmax = g_Tmax;
#pragma unroll
    for (int i = 0; i < 32; i++) {
        int seg = tid + i * 256;
        int r = seg >> 7, c8 = (seg & 127) * 8;
        cp16(WH + r * HSTRH + c8,
             Wh + ((size_t)((r >> 4) * H_ + j0 + (r & 15))) * H_ + c8);
    }
    cp_commit(); cp_wait<0>();
    grid_barrier(dir, ++epoch);

    const uint32_t HTu = s2u(HT);
    const uint32_t WHu = s2u(WH);
    const int kq  = warp >> 1;                    // k-quarter (0..3)
    const int nh  = warp & 1;                     // n-half (0/1)
    const int kb  = kq * 256;                     // k base (halves)
    const int rpA = (lane & 7) + ((lane >> 3) & 1) * 8;
    const int kpA = (lane >> 4) * 8;
    const uint32_t aB0 = HTu + ((0  + rpA) * HSTRH + kpA + kb) * 2;
    const uint32_t aB1 = HTu + ((16 + rpA) * HSTRH + kpA + kb) * 2;
    const int rpB = nh * 32 + (lane & 7) + (lane >> 4) * 8;
    const int kpB = ((lane >> 3) & 1) * 8;
    const uint32_t bB0 = WHu + (rpB * HSTRH + kpB + kb) * 2;
    const uint32_t bB1 = bB0 + 16 * HSTRH * 2;
    float* GSw = GSB + kq * 32 * 64;

    auto issueHC = [&](int colbase, int nrow8) {
        for (int i = 0; i < nrow8; i++) {
            int seg = tid + i * 256;
            int row = seg >> 5, c8 = (seg & 31) * 8;
            cp16(HT + row * HSTRH + colbase + c8, hdir + row * H_ + colbase + c8);
        }
    };

    auto prefetchXP = [&](int t, float xr[2][4], bool act[2]) {
#pragma unroll
        for (int p2 = 0; p2 < 2; p2++) {
            int p = tid + p2 * 256, b = p >> 4, jl = p & 15;
            act[p2] = (t < SLEN[b]);
            if (act[p2]) {
                int pb = SPRM[b];
                int teff = dir ? (SLEN[b] - 1 - t) : t;
                const float* xb = xp + ((size_t)(pb * T_ + teff)) * G4_ + j0 + jl;
                xr[p2][0] = __ldcs(xb);
                xr[p2][1] = __ldcs(xb + H_);
                xr[p2][2] = __ldcs(xb + 2 * H_);
                xr[p2][3] = __ldcs(xb + 3 * H_);
            }
        }
    };

    float xr[2][4];  bool act[2];
    float xrn[2][4]; bool actn[2];
    prefetchXP(0, xr, act);

    __half outh[2];
    int    outix[2];
    bool   outa[2] = { false, false };

    for (int t = 0; t < Tmax; t++) {
        const int nb = NBT[t];
        const bool full = nb > 16;
        const int nrow8 = (nb + 7) >> 3;          // 1..4 (8-row granularity)

        // issue h chunks in k order (quarter q consumes chunk q)
        issueHC(0,   nrow8); cp_commit();
        issueHC(256, nrow8); cp_commit();
        issueHC(512, nrow8); cp_commit();
        issueHC(768, nrow8); cp_commit();

        // deferred out writes from step t-1 (overlap h load)
        if (out) {
#pragma unroll
            for (int p2 = 0; p2 < 2; p2++)
                if (outa[p2]) out[outix[p2]] = outh[p2];
        }
        // prefetch next step's xp (overlaps MMA below)
        if (t + 1 < Tmax) prefetchXP(t + 1, xrn, actn);

        float acc[2][4][4];
#pragma unroll
        for (int a = 0; a < 2; a++)
#pragma unroll
            for (int b = 0; b < 4; b++)
#pragma unroll
                for (int k = 0; k < 4; k++) acc[a][b][k] = 0.f;

        // phase A: chunks 0,1 resident -> quarters 0,1 compute
        cp_wait<2>();
        __syncthreads();
        if (kq < 2) {
#pragma unroll 4
            for (int k = 0; k < 256; k += 16) {
                uint32_t a0[4], b0[4], b1[4];
                ldsm4(a0, aB0 + k * 2);
                ldsm4(b0, bB0 + k * 2);
                ldsm4(b1, bB1 + k * 2);
                mma16(acc[0][0], a0, b0);
                mma16(acc[0][1], a0, b0 + 2);
                mma16(acc[0][2], a0, b1);
                mma16(acc[0][3], a0, b1 + 2);
                if (full) {
                    uint32_t a1[4];
                    ldsm4(a1, aB1 + k * 2);
                    mma16(acc[1][0], a1, b0);
                    mma16(acc[1][1], a1, b0 + 2);
                    mma16(acc[1][2], a1, b1);
                    mma16(acc[1][3], a1, b1 + 2);
                }
            }
        }

        // phase B: chunks 2,3 resident -> quarters 2,3 compute
        cp_wait<0>();
        __syncthreads();
        if (kq >= 2) {
#pragma unroll 4
            for (int k = 0; k < 256; k += 16) {
                uint32_t a0[4], b0[4], b1[4];
                ldsm4(a0, aB0 + k * 2);
                ldsm4(b0, bB0 + k * 2);
                ldsm4(b1, bB1 + k * 2);
                mma16(acc[0][0], a0, b0);
                mma16(acc[0][1], a0, b0 + 2);
                mma16(acc[0][2], a0, b1);
                mma16(acc[0][3], a0, b1 + 2);
                if (full) {
                    uint32_t a1[4];
                    ldsm4(a1, aB1 + k * 2);
                    mma16(acc[1][0], a1, b0);
                    mma16(acc[1][1], a1, b0 + 2);
                    mma16(acc[1][2], a1, b1);
                    mma16(acc[1][3], a1, b1 + 2);
                }
            }
        }
        __syncthreads();     // all HT ldsm done before GS alias writes

        // dump gate partials: warp owns cols [nh*32, nh*32+32) of GSB[kq]
        {
            int rowb = lane >> 2, colb = nh * 32 + 2 * (lane & 3);
#pragma unroll
            for (int nt = 0; nt < 4; nt++) {
                GSw[rowb * 64 + colb + nt * 8]           = acc[0][nt][0];
                GSw[rowb * 64 + colb + nt * 8 + 1]       = acc[0][nt][1];
                GSw[(rowb + 8) * 64 + colb + nt * 8]     = acc[0][nt][2];
                GSw[(rowb + 8) * 64 + colb + nt * 8 + 1] = acc[0][nt][3];
            }
            if (full) {
#pragma unroll
                for (int nt = 0; nt < 4; nt++) {
                    GSw[(16 + rowb) * 64 + colb + nt * 8]     = acc[1][nt][0];
                    GSw[(16 + rowb) * 64 + colb + nt * 8 + 1] = acc[1][nt][1];
                    GSw[(24 + rowb) * 64 + colb + nt * 8]     = acc[1][nt][2];
                    GSw[(24 + rowb) * 64 + colb + nt * 8 + 1] = acc[1][nt][3];
                }
            }
        }
        __syncthreads();

        // LSTM cell (live rows only); sum the 4 k-quarter partials
#pragma unroll
        for (int p2 = 0; p2 < 2; p2++) {
            if (!act[p2]) { outa[p2] = false; continue; }
            int p = tid + p2 * 256, b = p >> 4, jl = p & 15;
            float gi = xr[p2][0], gf = xr[p2][1], gg = xr[p2][2], go = xr[p2][3];
#pragma unroll
            for (int q = 0; q < 4; q++) {
                const float* G = GSB + q * 32 * 64 + b * 64;
                gi += G[jl];
                gf += G[16 + jl];
                gg += G[32 + jl];
                go += G[48 + jl];
            }
            float ii = sigmoidf_(gi), ff = sigmoidf_(gf);
            float gv = tanhf(gg),     oo = sigmoidf_(go);
            float cn = ff * CST[p] + ii * gv;
            float hn = oo * tanhf(cn);
            CST[p] = cn; HST[p] = hn;
            __half hh = __float2half_rn(hn);
            hdir[b * H_ + j0 + jl] = hh;
            if (out) {
                int pb = SPRM[b];
                int pout = dir ? (SLEN[b] - 1 - t) : t;
                outh[p2] = hh;
                outix[p2] = (pb * T_ + pout) * (2 * H_) + dir * H_ + j0 + jl;
                outa[p2] = true;
            }
        }
        grid_barrier(dir, ++epoch);

#pragma unroll
        for (int p2 = 0; p2 < 2; p2++) {
            act[p2] = actn[p2];
#pragma unroll
            for (int q = 0; q < 4; q++) xr[p2][q] = xrn[p2][q];
        }
    }
    if (out) {
#pragma unroll
        for (int p2 = 0; p2 < 2; p2++)
            if (outa[p2]) out[outix[p2]] = outh[p2];
    }
}

// ---------------- kernel 4: final linear  out = [h2b, h2f] @ lin_w^T + b ---
__global__ __launch_bounds__(256) void final_linear_kernel(
    const __half* __restrict__ hF, const __half* __restrict__ hB,
    const float* __restrict__ lw, const float* __restrict__ lb,
    float* __restrict__ outp)
{
    int w = (blockIdx.x * blockDim.x + threadIdx.x) >> 5;
    int lane = threadIdx.x & 31;
    if (w >= B_ * 2) return;
    int b = w >> 1, c = w & 1;
    int pb = g_perm[b];
    float s = 0.f;
    for (int k = lane; k < 2 * H_; k += 32) {
        float xv = __half2float((k < H_) ? hB[b * H_ + k] : hF[b * H_ + (k - H_)]);
        s += xv * lw[c * 2 * H_ + k];
    }
#pragma unroll
    for (int o = 16; o; o >>= 1) s += __shfl_xor_sync(0xffffffffu, s, o);
    if (lane == 0) outp[pb * 2 + c] = s + lb[c];
}

// ---------------- launch ----------------------------------------------------
extern "C" void kernel_launch(void* const* d_in, const int* in_sizes, int n_in,
                              void* d_out, int out_size)
{
    const int*   tok      = (const int*)  d_in[0];
    const int*   lens     = (const int*)  d_in[1];
    const float* emb      = (const float*)d_in[2];
    const float* w_ih_l0f = (const float*)d_in[3];
    const float* w_hh_l0f = (const float*)d_in[4];
    const float* b_ih_l0f = (const float*)d_in[5];
    const float* b_hh_l0f = (const float*)d_in[6];
    const float* w_ih_l0b = (const float*)d_in[7];
    const float* w_hh_l0b = (const float*)d_in[8];
    const float* b_ih_l0b = (const float*)d_in[9];
    const float* b_hh_l0b = (const float*)d_in[10];
    const float* w_ih_l1f = (const float*)d_in[11];
    const float* w_hh_l1f = (const float*)d_in[12];
    const float* b_ih_l1f = (const float*)d_in[13];
    const float* b_hh_l1f = (const float*)d_in[14];
    const float* w_ih_l1b = (const float*)d_in[15];
    const float* w_hh_l1b = (const float*)d_in[16];
    const float* b_ih_l1b = (const float*)d_in[17];
    const float* b_hh_l1b = (const float*)d_in[18];
    const float* lin_w    = (const float*)d_in[19];
    const float* lin_b    = (const float*)d_in[20];

    __half *x, *wA, *wB, *whF, *whB, *out0, *hF, *hB;
    float *xpF, *xpB;
    cudaGetSymbolAddress((void**)&x,    g_x);
    cudaGetSymbolAddress((void**)&wA,   g_wA);
    cudaGetSymbolAddress((void**)&wB,   g_wB);
    cudaGetSymbolAddress((void**)&whF,  g_whF);
    cudaGetSymbolAddress((void**)&whB,  g_whB);
    cudaGetSymbolAddress((void**)&xpF,  g_xpF);
    cudaGetSymbolAddress((void**)&xpB,  g_xpB);
    cudaGetSymbolAddress((void**)&out0, g_out0);
    cudaGetSymbolAddress((void**)&hF,   g_hF);
    cudaGetSymbolAddress((void**)&hB,   g_hB);

    cudaFuncSetAttribute(gemm_f16, cudaFuncAttributeMaxDynamicSharedMemorySize, GEMM_SMEM);
    cudaFuncSetAttribute(lstm_layer_kernel, cudaFuncAttributeMaxDynamicSharedMemorySize, LSTM_SMEM);

    dim3 gg(G4_ / 128, M_ / 128);

    // compacted row index + sorted perm + nbt
    build_idx_kernel<<<1, 256>>>(lens);

    // embedding gather -> fp16, K padded to 320
    gather_kernel<<<(M_ * EP_ + 255) / 256, 256>>>(tok, emb, x);

    // layer-0 weight conversions, then input projections (Ka = 320)
    conv_f16_pad<<<(G4_ * EP_ + 255) / 256, 256>>>(w_ih_l0f, wA, G4_, E_, EP_);
    conv_f16_pad<<<(G4_ * EP_ + 255) / 256, 256>>>(w_ih_l0b, wB, G4_, E_, EP_);
    conv_f16_v4<<<(G4_ * H_ / 4 + 255) / 256, 256>>>((const float4*)w_hh_l0f, (__half2*)whF, G4_ * H_ / 4);
    conv_f16_v4<<<(G4_ * H_ / 4 + 255) / 256, 256>>>((const float4*)w_hh_l0b, (__half2*)whB, G4_ * H_ / 4);
    gemm_f16<<<gg, 256, GEMM_SMEM>>>(x, wA, b_ih_l0f, b_hh_l0f, xpF, EP_);
    gemm_f16<<<gg, 256, GEMM_SMEM>>>(x, wB, b_ih_l0b, b_hh_l0b, xpB, EP_);

    // layer-0 recurrence (writes [out_f || out_b] as fp16)
    lstm_layer_kernel<<<NCTA_REC, 256, LSTM_SMEM>>>(xpF, xpB, whF, whB, lens,
                                                    out0, hF, hB);

    // layer-1 weight conversions, then input projections (Ka = 2048)
    conv_f16_v4<<<(G4_ * 2048 / 4 + 255) / 256, 256>>>((const float4*)w_ih_l1f, (__half2*)wA, G4_ * 2048 / 4);
    conv_f16_v4<<<(G4_ * 2048 / 4 + 255) / 256, 256>>>((const float4*)w_ih_l1b, (__half2*)wB, G4_ * 2048 / 4);
    conv_f16_v4<<<(G4_ * H_ / 4 + 255) / 256, 256>>>((const float4*)w_hh_l1f, (__half2*)whF, G4_ * H_ / 4);
    conv_f16_v4<<<(G4_ * H_ / 4 + 255) / 256, 256>>>((const float4*)w_hh_l1b, (__half2*)whB, G4_ * H_ / 4);
    gemm_f16<<<gg, 256, GEMM_SMEM>>>(out0, wA, b_ih_l1f, b_hh_l1f, xpF, 2 * H_);
    gemm_f16<<<gg, 256, GEMM_SMEM>>>(out0, wB, b_ih_l1b, b_hh_l1b, xpB, 2 * H_);

    // layer-1 recurrence (only final hiddens needed)
    lstm_layer_kernel<<<NCTA_REC, 256, LSTM_SMEM>>>(xpF, xpB, whF, whB, lens,
                                                    (__half*)nullptr, hF, hB);

    // head
    final_linear_kernel<<<8, 256>>>(hF, hB, lin_w, lin_b, (float*)d_out);
}

// round 15
// speedup vs baseline: 1.0178x; 1.0178x over previous
#include <cuda_runtime.h>
#include <cuda_fp16.h>
#include <cstdint>
#include <cstddef>

// Problem constants
#define B_   32
#define T_   512
#define E_   300
#define EP_  320              // padded embedding K (mult of 32)
#define H_   1024
#define G4_  4096             // 4*H
#define M_   (B_*T_)          // 16384 token rows
#define NCTA_REC 128

// ---------------- scratch (device globals; no allocation allowed) ----------
__device__ __half   g_x   [(size_t)M_ * EP_];      // embedded inputs (fp16)
__device__ __half   g_wA  [(size_t)G4_ * 2048];    // converted w_ih (dir f)
__device__ __half   g_wB  [(size_t)G4_ * 2048];    // converted w_ih (dir b)
__device__ __half   g_whF [(size_t)G4_ * H_];      // converted w_hh fwd (fp16)
__device__ __half   g_whB [(size_t)G4_ * H_];      // converted w_hh bwd (fp16)
__device__ float    g_xpF [(size_t)M_ * G4_];      // input projection fwd
__device__ float    g_xpB [(size_t)M_ * G4_];      // input projection bwd
__device__ __half   g_out0[(size_t)M_ * 2 * H_];   // layer0 output (fp16)
__device__ __half   g_hF  [B_ * H_];               // sorted-row layout
__device__ __half   g_hB  [B_ * H_];
__device__ int      g_idx [M_];                    // compacted row -> b*T+t
__device__ int      g_Mc;                          // number of active rows
__device__ int      g_perm[B_];                    // sorted row -> orig batch
__device__ int      g_nbt [T_];                    // active batches at step t
__device__ int      g_Tmax;                        // max length
__device__ unsigned g_cnt [8 * 32];                // striped counters (4/dir)
__device__ unsigned g_cntm[2 * 32];                // master counter per dir
__device__ volatile unsigned g_bgen[2 * 32];       // barrier gen per dir

// ---------------- helpers ---------------------------------------------------
__device__ __forceinline__ void mma16(float* c, const uint32_t* a, const uint32_t* b) {
    asm volatile(
        "mma.sync.aligned.m16n8k16.row.col.f32.f16.f16.f32 "
        "{%0,%1,%2,%3},{%4,%5,%6,%7},{%8,%9},{%0,%1,%2,%3};"
        : "+f"(c[0]), "+f"(c[1]), "+f"(c[2]), "+f"(c[3])
        : "r"(a[0]), "r"(a[1]), "r"(a[2]), "r"(a[3]), "r"(b[0]), "r"(b[1]));
}

__device__ __forceinline__ void ldsm4(uint32_t* r, uint32_t addr) {
    asm volatile("ldmatrix.sync.aligned.m8n8.x4.shared.b16 {%0,%1,%2,%3}, [%4];"
        : "=r"(r[0]), "=r"(r[1]), "=r"(r[2]), "=r"(r[3]) : "r"(addr));
}

__device__ __forceinline__ float sigmoidf_(float x) { return 1.f / (1.f + __expf(-x)); }

__device__ __forceinline__ uint32_t s2u(const void* p) {
    uint32_t r;
    asm("{ .reg .u64 t; cvta.to.shared.u64 t, %1; cvt.u32.u64 %0, t; }" : "=r"(r) : "l"(p));
    return r;
}
__device__ __forceinline__ void cp16(void* smem, const void* gmem) {
    asm volatile("cp.async.cg.shared.global [%0], [%1], 16;\n" :: "r"(s2u(smem)), "l"(gmem));
}
__device__ __forceinline__ void cp_commit() { asm volatile("cp.async.commit_group;"); }
template<int N> __device__ __forceinline__ void cp_wait() {
    asm volatile("cp.async.wait_group %0;" :: "n"(N));
}

// Per-direction grid barrier: 64 CTAs per direction, 4 stripes of 16.
// Monotonic epochs: no resets, safe across kernel instances & graph replays.
__device__ __forceinline__ void grid_barrier(int dir, unsigned epoch) {
    __threadfence();
    __syncthreads();
    if (threadIdx.x == 0) {
        unsigned s = (dir * 4 + (blockIdx.x & 3)) * 32;
        unsigned v = atomicAdd(&g_cnt[s], 1u) + 1u;
        if (v == 16u * epoch) {
            unsigned a = atomicAdd(&g_cntm[dir * 32], 1u) + 1u;
            if (a == 4u * epoch) {
                __threadfence();
                g_bgen[dir * 32] = epoch;
            }
        }
        while (g_bgen[dir * 32] < epoch) { }
    }
    __syncthreads();
}

// ---------------- kernel 0: compacted index + sort + nbt -------------------
__global__ __launch_bounds__(256) void build_idx_kernel(const int* __restrict__ lens)
{
    __shared__ int sl[B_];
    __shared__ int offs[B_];
    int tid = threadIdx.x;
    if (tid < B_) sl[tid] = lens[tid];
    __syncthreads();
    if (tid == 0) {
        int s = 0;
        for (int b = 0; b < B_; b++) { offs[b] = s; s += sl[b]; }
        g_Mc = s;
        int pr[B_];
        for (int i = 0; i < B_; i++) pr[i] = i;
        for (int i = 0; i < B_; i++) {
            int best = i;
            for (int j = i + 1; j < B_; j++)
                if (sl[pr[j]] > sl[pr[best]]) best = j;
            int tmp = pr[i]; pr[i] = pr[best]; pr[best] = tmp;
        }
        int mx = 0;
        for (int i = 0; i < B_; i++) {
            g_perm[i] = pr[i];
            if (sl[i] > mx) mx = sl[i];
        }
        g_Tmax = mx;
    }
    __syncthreads();
    for (int t = tid; t < T_; t += 256) {
        int c = 0;
        for (int b = 0; b < B_; b++) c += (sl[b] > t);
        g_nbt[t] = c;
    }
    for (int b = 0; b < B_; b++) {
        int len = sl[b], o = offs[b];
        for (int t = tid; t < len; t += 256)
            g_idx[o + t] = b * T_ + t;
    }
}

// ---------------- kernel 1: embedding gather (emit fp16, pad to 320) -------
__global__ __launch_bounds__(256) void gather_kernel(
    const int* __restrict__ tok, const float* __restrict__ emb, __half* __restrict__ x)
{
    int i = blockIdx.x * 256 + threadIdx.x;
    if (i >= M_ * EP_) return;
    int bt = i / EP_;
    int e  = i - bt * EP_;
    x[i] = (e < E_) ? __float2half_rn(emb[(size_t)tok[bt] * E_ + e]) : __float2half(0.f);
}

// ---------------- kernel 1b: vectorized pad-convert for K=300 -> Kp=320 ----
// Each thread handles one 4-element group: 80 groups/row (75 data + 5 zero).
__global__ __launch_bounds__(256) void conv_f16_pad300(
    const float4* __restrict__ src, __half2* __restrict__ dst, int N)
{
    int i = blockIdx.x * 256 + threadIdx.x;
    if (i >= N * 80) return;
    int n = i / 80, g = i - n * 80;
    __half2 lo, hi;
    if (g < 75) {
        float4 v = src[(size_t)n * 75 + g];
        lo = __floats2half2_rn(v.x, v.y);
        hi = __floats2half2_rn(v.z, v.w);
    } else {
        lo = __floats2half2_rn(0.f, 0.f);
        hi = lo;
    }
    size_t d = ((size_t)n * 80 + g) * 2;
    dst[d]     = lo;
    dst[d + 1] = hi;
}

__global__ __launch_bounds__(256) void conv_f16_v4(
    const float4* __restrict__ src, __half2* __restrict__ dst, int n4)
{
    int i = blockIdx.x * 256 + threadIdx.x;
    if (i >= n4) return;
    float4 v = src[i];
    dst[2 * i]     = __floats2half2_rn(v.x, v.y);
    dst[2 * i + 1] = __floats2half2_rn(v.z, v.w);
}

// ---------------- kernel 2: fp16 GEMM over compacted rows ------------------
// 4-stage cp.async ring (prefetch distance 3), tiles 128x128x32.
#define GST 4
#define ASTR 40
#define GEMM_SMEM (2 * GST * 128 * ASTR * 2)
__global__ __launch_bounds__(256, 2) void gemm_f16(
    const __half* __restrict__ A, const __half* __restrict__ Bw,
    const float* __restrict__ bias1, const float* __restrict__ bias2,
    float* __restrict__ C, int Ka)
{
    extern __shared__ char smraw[];
    __half* As = (__half*)smraw;                  // GST * 128 * ASTR
    __half* Bs = As + GST * 128 * ASTR;

    const int tid = threadIdx.x, warp = tid >> 5, lane = tid & 31;
    const int m0 = blockIdx.y * 128, n0 = blockIdx.x * 128;
    const int Mc = g_Mc;
    if (m0 >= Mc) return;
    const int wm = (warp >> 1) * 32, wn = (warp & 1) * 64;
    const __half* Bg = Bw + (size_t)n0 * Ka;

    const __half* Arow[2];
#pragma unroll
    for (int i = 0; i < 2; i++) {
        int glob = m0 + (tid >> 2) + 64 * i;
        int src  = g_idx[glob < Mc ? glob : Mc - 1];
        Arow[i] = A + (size_t)src * Ka + (tid & 3) * 8;
    }

    float acc[2][8][4];
#pragma unroll
    for (int i = 0; i < 2; i++)
#pragma unroll
        for (int j = 0; j < 8; j++)
#pragma unroll
            for (int k = 0; k < 4; k++) acc[i][j][k] = 0.f;

    auto issue = [&](int st, int kc) {
#pragma unroll
        for (int i = 0; i < 2; i++) {
            int row = (tid >> 2) + 64 * i, c8 = (tid & 3) * 8;
            cp16(As + st * 128 * ASTR + row * ASTR + c8, Arow[i] + kc);
            cp16(Bs + st * 128 * ASTR + row * ASTR + c8, Bg + (size_t)row * Ka + kc + c8);
        }
    };

    const int nc = Ka >> 5;
    issue(0, 0);  cp_commit();
    if (nc > 1) issue(1, 32);  cp_commit();
    if (nc > 2) issue(2, 64);  cp_commit();

    const uint32_t Au = s2u(As), Bu = s2u(Bs);
    const int rpA = (lane & 7) + ((lane >> 3) & 1) * 8;
    const int kpA = (lane >> 4) * 8;
    const int rpB = (lane & 7) + (lane >> 4) * 8;
    const int kpB = ((lane >> 3) & 1) * 8;

    for (int c = 0; c < nc; c++) {
        if (c + 2 < nc) cp_wait<2>();
        else if (c + 1 < nc) cp_wait<1>();
        else cp_wait<0>();
        __syncthreads();
        if (c + 3 < nc) { issue((c + 3) % GST, (c + 3) * 32); cp_commit(); }

        const uint32_t ab = Au + (c % GST) * 128 * ASTR * 2;
        const uint32_t bb = Bu + (c % GST) * 128 * ASTR * 2;
#pragma unroll
        for (int kk = 0; kk < 32; kk += 16) {
            uint32_t af[2][4], bf[4][4];
#pragma unroll
            for (int mt = 0; mt < 2; mt++)
                ldsm4(af[mt], ab + ((wm + mt * 16 + rpA) * ASTR + kpA + kk) * 2);
#pragma unroll
            for (int nt4 = 0; nt4 < 4; nt4++)
                ldsm4(bf[nt4], bb + ((wn + nt4 * 16 + rpB) * ASTR + kpB + kk) * 2);
#pragma unroll
            for (int mt = 0; mt < 2; mt++)
#pragma unroll
                for (int nt4 = 0; nt4 < 4; nt4++) {
                    mma16(acc[mt][nt4 * 2],     af[mt], bf[nt4]);
                    mma16(acc[mt][nt4 * 2 + 1], af[mt], bf[nt4] + 2);
                }
        }
    }

    int rg[4]; size_t drow[4]; bool val[4];
#pragma unroll
    for (int mt = 0; mt < 2; mt++) {
        rg[mt * 2]     = m0 + wm + mt * 16 + (lane >> 2);
        rg[mt * 2 + 1] = rg[mt * 2] + 8;
    }
#pragma unroll
    for (int i = 0; i < 4; i++) {
        val[i]  = rg[i] < Mc;
        drow[i] = val[i] ? (size_t)g_idx[rg[i]] * G4_ : 0;
    }
#pragma unroll
    for (int mt = 0; mt < 2; mt++)
#pragma unroll
        for (int nt = 0; nt < 8; nt++) {
            int col = n0 + wn + nt * 8 + 2 * (lane & 3);
            float bv0 = bias1[col] + bias2[col];
            float bv1 = bias1[col + 1] + bias2[col + 1];
            if (val[mt * 2]) {
                C[drow[mt * 2] + col]     = acc[mt][nt][0] + bv0;
                C[drow[mt * 2] + col + 1] = acc[mt][nt][1] + bv1;
            }
            if (val[mt * 2 + 1]) {
                C[drow[mt * 2 + 1] + col]     = acc[mt][nt][2] + bv0;
                C[drow[mt * 2 + 1] + col + 1] = acc[mt][nt][3] + bv1;
            }
        }
}

// ---------------- kernel 3: persistent bi-LSTM layer (fp16, resident W) ----
// 8 warps = 4 k-quarters (k=256) x 2 n-halves (n=32). Gate partials alias the
// h tile. Two phases: quarters 0-1 compute on chunks 0-1 while 2-3 stream.
#define HSTRH 1032            // half-stride, mod 64 == 8 -> conflict-free ldsm
#define LSTM_SMEM ((64 + 32) * HSTRH * 2 + 512*4 + 512*4 + T_*4 + 64*4 + 128)
__global__ __launch_bounds__(256) void lstm_layer_kernel(
    const float* __restrict__ xpF, const float* __restrict__ xpB,
    const __half* __restrict__ WhF, const __half* __restrict__ WhB,
    const int* __restrict__ lengths,
    __half* __restrict__ out,             // (B*T) x 2H fp16, or nullptr
    __half* __restrict__ hF, __half* __restrict__ hB)
{
    extern __shared__ char smraw[];
    __half* WH  = (__half*)smraw;                 // [64][HSTRH] resident W
    __half* HT  = WH + 64 * HSTRH;                // [32][HSTRH] h tile
    float*  GSB = (float*)HT;                     // [4][32][64] gate partials (ALIAS)
    float*  CST = (float*)(HT + 32 * HSTRH);      // [512]
    float*  HST = CST + 512;                      // [512]
    int*    NBT = (int*)(HST + 512);              // [T_]
    int*    SLEN = NBT + T_;                      // [32] sorted lengths
    int*    SPRM = SLEN + 32;                     // [32] sorted -> orig batch

    const int tid = threadIdx.x, warp = tid >> 5, lane = tid & 31;
    const int cta = blockIdx.x;
    const int dir = cta >> 6;
    const int j0  = (cta & 63) * 16;
    const float*  xp   = dir ? xpB : xpF;
    const __half* Wh   = dir ? WhB : WhF;
    __half*       hdir = dir ? hB : hF;

    unsigned epoch = g_bgen[dir * 32];

    for (int p = tid; p < 512; p += 256) {
        int b = p >> 4, jl = p & 15;
        CST[p] = 0.f; HST[p] = 0.f;
        hdir[b * H_ + j0 + jl] = __float2half(0.f);
    }
    if (tid < 32) {
        int pb = g_perm[tid];
        SPRM[tid] = pb;
        SLEN[tid] = lengths[pb];
    }
    for (int i = tid; i < T_; i += 256) NBT[i] = g_nbt[i];
    const int Tmax = g_Tmax;
#pragma unroll
    for (int i = 0; i < 32; i++) {
        int seg = tid + i * 256;
        int r = seg >> 7, c8 = (seg & 127) * 8;
        cp16(WH + r * HSTRH + c8,
             Wh + ((size_t)((r >> 4) * H_ + j0 + (r & 15))) * H_ + c8);
    }
    cp_commit(); cp_wait<0>();
    grid_barrier(dir, ++epoch);

    const uint32_t HTu = s2u(HT);
    const uint32_t WHu = s2u(WH);
    const int kq  = warp >> 1;                    // k-quarter (0..3)
    const int nh  = warp & 1;                     // n-half (0/1)
    const int kb  = kq * 256;                     // k base (halves)
    const int rpA = (lane & 7) + ((lane >> 3) & 1) * 8;
    const int kpA = (lane >> 4) * 8;
    const uint32_t aB0 = HTu + ((0  + rpA) * HSTRH + kpA + kb) * 2;
    const uint32_t aB1 = HTu + ((16 + rpA) * HSTRH + kpA + kb) * 2;
    const int rpB = nh * 32 + (lane & 7) + (lane >> 4) * 8;
    const int kpB = ((lane >> 3) & 1) * 8;
    const uint32_t bB0 = WHu + (rpB * HSTRH + kpB + kb) * 2;
    const uint32_t bB1 = bB0 + 16 * HSTRH * 2;
    float* GSw = GSB + kq * 32 * 64;

    auto issueHC = [&](int colbase, int nrow8) {
        for (int i = 0; i < nrow8; i++) {
            int seg = tid + i * 256;
            int row = seg >> 5, c8 = (seg & 31) * 8;
            cp16(HT + row * HSTRH + colbase + c8, hdir + row * H_ + colbase + c8);
        }
    };

    auto prefetchXP = [&](int t, float xr[2][4], bool act[2]) {
#pragma unroll
        for (int p2 = 0; p2 < 2; p2++) {
            int p = tid + p2 * 256, b = p >> 4, jl = p & 15;
            act[p2] = (t < SLEN[b]);
            if (act[p2]) {
                int pb = SPRM[b];
                int teff = dir ? (SLEN[b] - 1 - t) : t;
                const float* xb = xp + ((size_t)(pb * T_ + teff)) * G4_ + j0 + jl;
                xr[p2][0] = __ldcs(xb);
                xr[p2][1] = __ldcs(xb + H_);
                xr[p2][2] = __ldcs(xb + 2 * H_);
                xr[p2][3] = __ldcs(xb + 3 * H_);
            }
        }
    };

    float xr[2][4];  bool act[2];
    float xrn[2][4]; bool actn[2];
    prefetchXP(0, xr, act);

    __half outh[2];
    int    outix[2];
    bool   outa[2] = { false, false };

    for (int t = 0; t < Tmax; t++) {
        const int nb = NBT[t];
        const bool full = nb > 16;
        const int nrow8 = full ? 4 : 2;

        // issue h chunks in k order (quarter q consumes chunk q)
        issueHC(0,   nrow8); cp_commit();
        issueHC(256, nrow8); cp_commit();
        issueHC(512, nrow8); cp_commit();
        issueHC(768, nrow8); cp_commit();

        // deferred out writes from step t-1 (overlap h load)
        if (out) {
#pragma unroll
            for (int p2 = 0; p2 < 2; p2++)
                if (outa[p2]) out[outix[p2]] = outh[p2];
        }
        // prefetch next step's xp (overlaps MMA below)
        if (t + 1 < Tmax) prefetchXP(t + 1, xrn, actn);

        float acc[2][4][4];
#pragma unroll
        for (int a = 0; a < 2; a++)
#pragma unroll
            for (int b = 0; b < 4; b++)
#pragma unroll
                for (int k = 0; k < 4; k++) acc[a][b][k] = 0.f;

        // phase A: chunks 0,1 resident -> quarters 0,1 compute
        cp_wait<2>();
        __syncthreads();
        if (kq < 2) {
#pragma unroll 4
            for (int k = 0; k < 256; k += 16) {
                uint32_t a0[4], b0[4], b1[4];
                ldsm4(a0, aB0 + k * 2);
                ldsm4(b0, bB0 + k * 2);
                ldsm4(b1, bB1 + k * 2);
                mma16(acc[0][0], a0, b0);
                mma16(acc[0][1], a0, b0 + 2);
                mma16(acc[0][2], a0, b1);
                mma16(acc[0][3], a0, b1 + 2);
                if (full) {
                    uint32_t a1[4];
                    ldsm4(a1, aB1 + k * 2);
                    mma16(acc[1][0], a1, b0);
                    mma16(acc[1][1], a1, b0 + 2);
                    mma16(acc[1][2], a1, b1);
                    mma16(acc[1][3], a1, b1 + 2);
                }
            }
        }

        // phase B: chunks 2,3 resident -> quarters 2,3 compute
        cp_wait<0>();
        __syncthreads();
        if (kq >= 2) {
#pragma unroll 4
            for (int k = 0; k < 256; k += 16) {
                uint32_t a0[4], b0[4], b1[4];
                ldsm4(a0, aB0 + k * 2);
                ldsm4(b0, bB0 + k * 2);
                ldsm4(b1, bB1 + k * 2);
                mma16(acc[0][0], a0, b0);
                mma16(acc[0][1], a0, b0 + 2);
                mma16(acc[0][2], a0, b1);
                mma16(acc[0][3], a0, b1 + 2);
                if (full) {
                    uint32_t a1[4];
                    ldsm4(a1, aB1 + k * 2);
                    mma16(acc[1][0], a1, b0);
                    mma16(acc[1][1], a1, b0 + 2);
                    mma16(acc[1][2], a1, b1);
                    mma16(acc[1][3], a1, b1 + 2);
                }
            }
        }
        __syncthreads();     // all HT ldsm done before GS alias writes

        // dump gate partials: warp owns cols [nh*32, nh*32+32) of GSB[kq]
        {
            int rowb = lane >> 2, colb = nh * 32 + 2 * (lane & 3);
#pragma unroll
            for (int nt = 0; nt < 4; nt++) {
                GSw[rowb * 64 + colb + nt * 8]           = acc[0][nt][0];
                GSw[rowb * 64 + colb + nt * 8 + 1]       = acc[0][nt][1];
                GSw[(rowb + 8) * 64 + colb + nt * 8]     = acc[0][nt][2];
                GSw[(rowb + 8) * 64 + colb + nt * 8 + 1] = acc[0][nt][3];
            }
            if (full) {
#pragma unroll
                for (int nt = 0; nt < 4; nt++) {
                    GSw[(16 + rowb) * 64 + colb + nt * 8]     = acc[1][nt][0];
                    GSw[(16 + rowb) * 64 + colb + nt * 8 + 1] = acc[1][nt][1];
                    GSw[(24 + rowb) * 64 + colb + nt * 8]     = acc[1][nt][2];
                    GSw[(24 + rowb) * 64 + colb + nt * 8 + 1] = acc[1][nt][3];
                }
            }
        }
        __syncthreads();

        // LSTM cell (live rows only); sum the 4 k-quarter partials
#pragma unroll
        for (int p2 = 0; p2 < 2; p2++) {
            if (!act[p2]) { outa[p2] = false; continue; }
            int p = tid + p2 * 256, b = p >> 4, jl = p & 15;
            float gi = xr[p2][0], gf = xr[p2][1], gg = xr[p2][2], go = xr[p2][3];
#pragma unroll
            for (int q = 0; q < 4; q++) {
                const float* G = GSB + q * 32 * 64 + b * 64;
                gi += G[jl];
                gf += G[16 + jl];
                gg += G[32 + jl];
                go += G[48 + jl];
            }
            float ii = sigmoidf_(gi), ff = sigmoidf_(gf);
            float gv = tanhf(gg),     oo = sigmoidf_(go);
            float cn = ff * CST[p] + ii * gv;
            float hn = oo * tanhf(cn);
            CST[p] = cn; HST[p] = hn;
            __half hh = __float2half_rn(hn);
            hdir[b * H_ + j0 + jl] = hh;
            if (out) {
                int pb = SPRM[b];
                int pout = dir ? (SLEN[b] - 1 - t) : t;
                outh[p2] = hh;
                outix[p2] = (pb * T_ + pout) * (2 * H_) + dir * H_ + j0 + jl;
                outa[p2] = true;
            }
        }
        grid_barrier(dir, ++epoch);

#pragma unroll
        for (int p2 = 0; p2 < 2; p2++) {
            act[p2] = actn[p2];
#pragma unroll
            for (int q = 0; q < 4; q++) xr[p2][q] = xrn[p2][q];
        }
    }
    if (out) {
#pragma unroll
        for (int p2 = 0; p2 < 2; p2++)
            if (outa[p2]) out[outix[p2]] = outh[p2];
    }
}

// ---------------- kernel 4: final linear  out = [h2b, h2f] @ lin_w^T + b ---
__global__ __launch_bounds__(256) void final_linear_kernel(
    const __half* __restrict__ hF, const __half* __restrict__ hB,
    const float* __restrict__ lw, const float* __restrict__ lb,
    float* __restrict__ outp)
{
    int w = (blockIdx.x * blockDim.x + threadIdx.x) >> 5;
    int lane = threadIdx.x & 31;
    if (w >= B_ * 2) return;
    int b = w >> 1, c = w & 1;
    int pb = g_perm[b];
    float s = 0.f;
    for (int k = lane; k < 2 * H_; k += 32) {
        float xv = __half2float((k < H_) ? hB[b * H_ + k] : hF[b * H_ + (k - H_)]);
        s += xv * lw[c * 2 * H_ + k];
    }
#pragma unroll
    for (int o = 16; o; o >>= 1) s += __shfl_xor_sync(0xffffffffu, s, o);
    if (lane == 0) outp[pb * 2 + c] = s + lb[c];
}

// ---------------- launch ----------------------------------------------------
extern "C" void kernel_launch(void* const* d_in, const int* in_sizes, int n_in,
                              void* d_out, int out_size)
{
    const int*   tok      = (const int*)  d_in[0];
    const int*   lens     = (const int*)  d_in[1];
    const float* emb      = (const float*)d_in[2];
    const float* w_ih_l0f = (const float*)d_in[3];
    const float* w_hh_l0f = (const float*)d_in[4];
    const float* b_ih_l0f = (const float*)d_in[5];
    const float* b_hh_l0f = (const float*)d_in[6];
    const float* w_ih_l0b = (const float*)d_in[7];
    const float* w_hh_l0b = (const float*)d_in[8];
    const float* b_ih_l0b = (const float*)d_in[9];
    const float* b_hh_l0b = (const float*)d_in[10];
    const float* w_ih_l1f = (const float*)d_in[11];
    const float* w_hh_l1f = (const float*)d_in[12];
    const float* b_ih_l1f = (const float*)d_in[13];
    const float* b_hh_l1f = (const float*)d_in[14];
    const float* w_ih_l1b = (const float*)d_in[15];
    const float* w_hh_l1b = (const float*)d_in[16];
    const float* b_ih_l1b = (const float*)d_in[17];
    const float* b_hh_l1b = (const float*)d_in[18];
    const float* lin_w    = (const float*)d_in[19];
    const float* lin_b    = (const float*)d_in[20];

    __half *x, *wA, *wB, *whF, *whB, *out0, *hF, *hB;
    float *xpF, *xpB;
    cudaGetSymbolAddress((void**)&x,    g_x);
    cudaGetSymbolAddress((void**)&wA,   g_wA);
    cudaGetSymbolAddress((void**)&wB,   g_wB);
    cudaGetSymbolAddress((void**)&whF,  g_whF);
    cudaGetSymbolAddress((void**)&whB,  g_whB);
    cudaGetSymbolAddress((void**)&xpF,  g_xpF);
    cudaGetSymbolAddress((void**)&xpB,  g_xpB);
    cudaGetSymbolAddress((void**)&out0, g_out0);
    cudaGetSymbolAddress((void**)&hF,   g_hF);
    cudaGetSymbolAddress((void**)&hB,   g_hB);

    cudaFuncSetAttribute(gemm_f16, cudaFuncAttributeMaxDynamicSharedMemorySize, GEMM_SMEM);
    cudaFuncSetAttribute(lstm_layer_kernel, cudaFuncAttributeMaxDynamicSharedMemorySize, LSTM_SMEM);

    dim3 gg(G4_ / 128, M_ / 128);

    // compacted row index + sorted perm + nbt
    build_idx_kernel<<<1, 256>>>(lens);

    // embedding gather -> fp16, K padded to 320
    gather_kernel<<<(M_ * EP_ + 255) / 256, 256>>>(tok, emb, x);

    // layer-0 weight conversions, then input projections (Ka = 320)
    conv_f16_pad300<<<(G4_ * 80 + 255) / 256, 256>>>((const float4*)w_ih_l0f, (__half2*)wA, G4_);
    conv_f16_pad300<<<(G4_ * 80 + 255) / 256, 256>>>((const float4*)w_ih_l0b, (__half2*)wB, G4_);
    conv_f16_v4<<<(G4_ * H_ / 4 + 255) / 256, 256>>>((const float4*)w_hh_l0f, (__half2*)whF, G4_ * H_ / 4);
    conv_f16_v4<<<(G4_ * H_ / 4 + 255) / 256, 256>>>((const float4*)w_hh_l0b, (__half2*)whB, G4_ * H_ / 4);
    gemm_f16<<<gg, 256, GEMM_SMEM>>>(x, wA, b_ih_l0f, b_hh_l0f, xpF, EP_);
    gemm_f16<<<gg, 256, GEMM_SMEM>>>(x, wB, b_ih_l0b, b_hh_l0b, xpB, EP_);

    // layer-0 recurrence (writes [out_f || out_b] as fp16)
    lstm_layer_kernel<<<NCTA_REC, 256, LSTM_SMEM>>>(xpF, xpB, whF, whB, lens,
                                                    out0, hF, hB);

    // layer-1 weight conversions, then input projections (Ka = 2048)
    conv_f16_v4<<<(G4_ * 2048 / 4 + 255) / 256, 256>>>((const float4*)w_ih_l1f, (__half2*)wA, G4_ * 2048 / 4);
    conv_f16_v4<<<(G4_ * 2048 / 4 + 255) / 256, 256>>>((const float4*)w_ih_l1b, (__half2*)wB, G4_ * 2048 / 4);
    conv_f16_v4<<<(G4_ * H_ / 4 + 255) / 256, 256>>>((const float4*)w_hh_l1f, (__half2*)whF, G4_ * H_ / 4);
    conv_f16_v4<<<(G4_ * H_ / 4 + 255) / 256, 256>>>((const float4*)w_hh_l1b, (__half2*)whB, G4_ * H_ / 4);
    gemm_f16<<<gg, 256, GEMM_SMEM>>>(out0, wA, b_ih_l1f, b_hh_l1f, xpF, 2 * H_);
    gemm_f16<<<gg, 256, GEMM_SMEM>>>(out0, wB, b_ih_l1b, b_hh_l1b, xpB, 2 * H_);

    // layer-1 recurrence (only final hiddens needed)
    lstm_layer_kernel<<<NCTA_REC, 256, LSTM_SMEM>>>(xpF, xpB, whF, whB, lens,
                                                    (__half*)nullptr, hF, hB);

    // head
    final_linear_kernel<<<8, 256>>>(hF, hB, lin_w, lin_b, (float*)d_out);
}

// round 16
// speedup vs baseline: 1.0327x; 1.0146x over previous
#include <cuda_runtime.h>
#include <cuda_fp16.h>
#include <cstdint>
#include <cstddef>

// Problem constants
#define B_   32
#define T_   512
#define E_   300
#define EP_  320              // padded embedding K (mult of 32)
#define H_   1024
#define G4_  4096             // 4*H
#define M_   (B_*T_)          // 16384 token rows
#define NCTA_REC 128

// ---------------- scratch (device globals; no allocation allowed) ----------
__device__ __half   g_x   [(size_t)M_ * EP_];      // embedded inputs (fp16)
__device__ __half   g_wA  [(size_t)G4_ * 2048];    // converted w_ih (dir f)
__device__ __half   g_wB  [(size_t)G4_ * 2048];    // converted w_ih (dir b)
__device__ __half   g_whF [(size_t)G4_ * H_];      // converted w_hh fwd (fp16)
__device__ __half   g_whB [(size_t)G4_ * H_];      // converted w_hh bwd (fp16)
__device__ float    g_xpF [(size_t)M_ * G4_];      // input projection fwd
__device__ float    g_xpB [(size_t)M_ * G4_];      // input projection bwd
__device__ __half   g_out0[(size_t)M_ * 2 * H_];   // layer0 output (fp16)
__device__ __half   g_hF  [B_ * H_];               // sorted-row layout
__device__ __half   g_hB  [B_ * H_];
__device__ int      g_idx [M_];                    // compacted row -> b*T+t
__device__ int      g_Mc;                          // number of active rows
__device__ int      g_perm[B_];                    // sorted row -> orig batch
__device__ int      g_nbt [T_];                    // active batches at step t
__device__ int      g_Tmax;                        // max length
__device__ unsigned g_cnt [8 * 32];                // striped counters (4/dir)
__device__ unsigned g_cntm[2 * 32];                // master counter per dir
__device__ volatile unsigned g_bgen[2 * 32];       // barrier gen per dir

// ---------------- helpers ---------------------------------------------------
__device__ __forceinline__ void mma16(float* c, const uint32_t* a, const uint32_t* b) {
    asm volatile(
        "mma.sync.aligned.m16n8k16.row.col.f32.f16.f16.f32 "
        "{%0,%1,%2,%3},{%4,%5,%6,%7},{%8,%9},{%0,%1,%2,%3};"
        : "+f"(c[0]), "+f"(c[1]), "+f"(c[2]), "+f"(c[3])
        : "r"(a[0]), "r"(a[1]), "r"(a[2]), "r"(a[3]), "r"(b[0]), "r"(b[1]));
}

__device__ __forceinline__ void ldsm4(uint32_t* r, uint32_t addr) {
    asm volatile("ldmatrix.sync.aligned.m8n8.x4.shared.b16 {%0,%1,%2,%3}, [%4];"
        : "=r"(r[0]), "=r"(r[1]), "=r"(r[2]), "=r"(r[3]) : "r"(addr));
}

__device__ __forceinline__ float sigmoidf_(float x) { return 1.f / (1.f + __expf(-x)); }

__device__ __forceinline__ uint32_t s2u(const void* p) {
    uint32_t r;
    asm("{ .reg .u64 t; cvta.to.shared.u64 t, %1; cvt.u32.u64 %0, t; }" : "=r"(r) : "l"(p));
    return r;
}
__device__ __forceinline__ void cp16(void* smem, const void* gmem) {
    asm volatile("cp.async.cg.shared.global [%0], [%1], 16;\n" :: "r"(s2u(smem)), "l"(gmem));
}
__device__ __forceinline__ void cp_commit() { asm volatile("cp.async.commit_group;"); }
template<int N> __device__ __forceinline__ void cp_wait() {
    asm volatile("cp.async.wait_group %0;" :: "n"(N));
}

// Per-direction grid barrier: 64 CTAs per direction, 4 stripes of 16.
// Monotonic epochs: no resets, safe across kernel instances & graph replays.
__device__ __forceinline__ void grid_barrier(int dir, unsigned epoch) {
    __threadfence();
    __syncthreads();
    if (threadIdx.x == 0) {
        unsigned s = (dir * 4 + (blockIdx.x & 3)) * 32;
        unsigned v = atomicAdd(&g_cnt[s], 1u) + 1u;
        if (v == 16u * epoch) {
            unsigned a = atomicAdd(&g_cntm[dir * 32], 1u) + 1u;
            if (a == 4u * epoch) {
                __threadfence();
                g_bgen[dir * 32] = epoch;
            }
        }
        while (g_bgen[dir * 32] < epoch) { }
    }
    __syncthreads();
}

// ---------------- kernel 0: compacted index + sort + nbt -------------------
__global__ __launch_bounds__(256) void build_idx_kernel(const int* __restrict__ lens)
{
    __shared__ int sl[B_];
    __shared__ int offs[B_];
    int tid = threadIdx.x;
    if (tid < B_) sl[tid] = lens[tid];
    __syncthreads();
    if (tid == 0) {
        int s = 0;
        for (int b = 0; b < B_; b++) { offs[b] = s; s += sl[b]; }
        g_Mc = s;
        int pr[B_];
        for (int i = 0; i < B_; i++) pr[i] = i;
        for (int i = 0; i < B_; i++) {
            int best = i;
            for (int j = i + 1; j < B_; j++)
                if (sl[pr[j]] > sl[pr[best]]) best = j;
            int tmp = pr[i]; pr[i] = pr[best]; pr[best] = tmp;
        }
        int mx = 0;
        for (int i = 0; i < B_; i++) {
            g_perm[i] = pr[i];
            if (sl[i] > mx) mx = sl[i];
        }
        g_Tmax = mx;
    }
    __syncthreads();
    for (int t = tid; t < T_; t += 256) {
        int c = 0;
        for (int b = 0; b < B_; b++) c += (sl[b] > t);
        g_nbt[t] = c;
    }
    for (int b = 0; b < B_; b++) {
        int len = sl[b], o = offs[b];
        for (int t = tid; t < len; t += 256)
            g_idx[o + t] = b * T_ + t;
    }
}

// ---------------- kernel 1: embedding gather (emit fp16, pad to 320) -------
__global__ __launch_bounds__(256) void gather_kernel(
    const int* __restrict__ tok, const float* __restrict__ emb, __half* __restrict__ x)
{
    int i = blockIdx.x * 256 + threadIdx.x;
    if (i >= M_ * EP_) return;
    int bt = i / EP_;
    int e  = i - bt * EP_;
    x[i] = (e < E_) ? __float2half_rn(emb[(size_t)tok[bt] * E_ + e]) : __float2half(0.f);
}

// ---------------- kernel 1b: vectorized pad-convert for K=300 -> Kp=320 ----
__global__ __launch_bounds__(256) void conv_f16_pad300(
    const float4* __restrict__ src, __half2* __restrict__ dst, int N)
{
    int i = blockIdx.x * 256 + threadIdx.x;
    if (i >= N * 80) return;
    int n = i / 80, g = i - n * 80;
    __half2 lo, hi;
    if (g < 75) {
        float4 v = src[(size_t)n * 75 + g];
        lo = __floats2half2_rn(v.x, v.y);
        hi = __floats2half2_rn(v.z, v.w);
    } else {
        lo = __floats2half2_rn(0.f, 0.f);
        hi = lo;
    }
    size_t d = ((size_t)n * 80 + g) * 2;
    dst[d]     = lo;
    dst[d + 1] = hi;
}

__global__ __launch_bounds__(256) void conv_f16_v4(
    const float4* __restrict__ src, __half2* __restrict__ dst, int n4)
{
    int i = blockIdx.x * 256 + threadIdx.x;
    if (i >= n4) return;
    float4 v = src[i];
    dst[2 * i]     = __floats2half2_rn(v.x, v.y);
    dst[2 * i + 1] = __floats2half2_rn(v.z, v.w);
}

// ---------------- kernel 2: fp16 GEMM over compacted rows ------------------
// 4-stage cp.async ring (prefetch distance 3), tiles 128x128x32.
#define GST 4
#define ASTR 40
#define GEMM_SMEM (2 * GST * 128 * ASTR * 2)
__global__ __launch_bounds__(256, 2) void gemm_f16(
    const __half* __restrict__ A, const __half* __restrict__ Bw,
    const float* __restrict__ bias1, const float* __restrict__ bias2,
    float* __restrict__ C, int Ka)
{
    extern __shared__ char smraw[];
    __half* As = (__half*)smraw;                  // GST * 128 * ASTR
    __half* Bs = As + GST * 128 * ASTR;

    const int tid = threadIdx.x, warp = tid >> 5, lane = tid & 31;
    const int m0 = blockIdx.y * 128, n0 = blockIdx.x * 128;
    const int Mc = g_Mc;
    if (m0 >= Mc) return;
    const int wm = (warp >> 1) * 32, wn = (warp & 1) * 64;
    const __half* Bg = Bw + (size_t)n0 * Ka;

    const __half* Arow[2];
#pragma unroll
    for (int i = 0; i < 2; i++) {
        int glob = m0 + (tid >> 2) + 64 * i;
        int src  = g_idx[glob < Mc ? glob : Mc - 1];
        Arow[i] = A + (size_t)src * Ka + (tid & 3) * 8;
    }

    float acc[2][8][4];
#pragma unroll
    for (int i = 0; i < 2; i++)
#pragma unroll
        for (int j = 0; j < 8; j++)
#pragma unroll
            for (int k = 0; k < 4; k++) acc[i][j][k] = 0.f;

    auto issue = [&](int st, int kc) {
#pragma unroll
        for (int i = 0; i < 2; i++) {
            int row = (tid >> 2) + 64 * i, c8 = (tid & 3) * 8;
            cp16(As + st * 128 * ASTR + row * ASTR + c8, Arow[i] + kc);
            cp16(Bs + st * 128 * ASTR + row * ASTR + c8, Bg + (size_t)row * Ka + kc + c8);
        }
    };

    const int nc = Ka >> 5;
    issue(0, 0);  cp_commit();
    if (nc > 1) issue(1, 32);  cp_commit();
    if (nc > 2) issue(2, 64);  cp_commit();

    const uint32_t Au = s2u(As), Bu = s2u(Bs);
    const int rpA = (lane & 7) + ((lane >> 3) & 1) * 8;
    const int kpA = (lane >> 4) * 8;
    const int rpB = (lane & 7) + (lane >> 4) * 8;
    const int kpB = ((lane >> 3) & 1) * 8;

    for (int c = 0; c < nc; c++) {
        if (c + 2 < nc) cp_wait<2>();
        else if (c + 1 < nc) cp_wait<1>();
        else cp_wait<0>();
        __syncthreads();
        if (c + 3 < nc) { issue((c + 3) % GST, (c + 3) * 32); cp_commit(); }

        const uint32_t ab = Au + (c % GST) * 128 * ASTR * 2;
        const uint32_t bb = Bu + (c % GST) * 128 * ASTR * 2;
#pragma unroll
        for (int kk = 0; kk < 32; kk += 16) {
            uint32_t af[2][4], bf[4][4];
#pragma unroll
            for (int mt = 0; mt < 2; mt++)
                ldsm4(af[mt], ab + ((wm + mt * 16 + rpA) * ASTR + kpA + kk) * 2);
#pragma unroll
            for (int nt4 = 0; nt4 < 4; nt4++)
                ldsm4(bf[nt4], bb + ((wn + nt4 * 16 + rpB) * ASTR + kpB + kk) * 2);
#pragma unroll
            for (int mt = 0; mt < 2; mt++)
#pragma unroll
                for (int nt4 = 0; nt4 < 4; nt4++) {
                    mma16(acc[mt][nt4 * 2],     af[mt], bf[nt4]);
                    mma16(acc[mt][nt4 * 2 + 1], af[mt], bf[nt4] + 2);
                }
        }
    }

    int rg[4]; size_t drow[4]; bool val[4];
#pragma unroll
    for (int mt = 0; mt < 2; mt++) {
        rg[mt * 2]     = m0 + wm + mt * 16 + (lane >> 2);
        rg[mt * 2 + 1] = rg[mt * 2] + 8;
    }
#pragma unroll
    for (int i = 0; i < 4; i++) {
        val[i]  = rg[i] < Mc;
        drow[i] = val[i] ? (size_t)g_idx[rg[i]] * G4_ : 0;
    }
#pragma unroll
    for (int mt = 0; mt < 2; mt++)
#pragma unroll
        for (int nt = 0; nt < 8; nt++) {
            int col = n0 + wn + nt * 8 + 2 * (lane & 3);
            float bv0 = bias1[col] + bias2[col];
            float bv1 = bias1[col + 1] + bias2[col + 1];
            if (val[mt * 2]) {
                C[drow[mt * 2] + col]     = acc[mt][nt][0] + bv0;
                C[drow[mt * 2] + col + 1] = acc[mt][nt][1] + bv1;
            }
            if (val[mt * 2 + 1]) {
                C[drow[mt * 2 + 1] + col]     = acc[mt][nt][2] + bv0;
                C[drow[mt * 2 + 1] + col + 1] = acc[mt][nt][3] + bv1;
            }
        }
}

// ---------------- kernel 3: persistent bi-LSTM layer -----------------------
// 8 warps = 4 k-quarters (k=256) x 2 n-halves (n=32). W fragments are hoisted
// into REGISTERS once before the time loop (128 regs/thread) -- per step only
// the h (A) fragments are ldsm'd. Gate partials alias the h tile. Two phases:
// quarters 0-1 compute on chunks 0-1 while chunks 2-3 stream.
#define HSTRH 1032            // half-stride, mod 64 == 8 -> conflict-free ldsm
#define LSTM_SMEM ((64 + 32) * HSTRH * 2 + 512*4 + 512*4 + T_*4 + 64*4 + 128)
__global__ __launch_bounds__(256) void lstm_layer_kernel(
    const float* __restrict__ xpF, const float* __restrict__ xpB,
    const __half* __restrict__ WhF, const __half* __restrict__ WhB,
    const int* __restrict__ lengths,
    __half* __restrict__ out,             // (B*T) x 2H fp16, or nullptr
    __half* __restrict__ hF, __half* __restrict__ hB)
{
    extern __shared__ char smraw[];
    __half* WH  = (__half*)smraw;                 // [64][HSTRH] resident W
    __half* HT  = WH + 64 * HSTRH;                // [32][HSTRH] h tile
    float*  GSB = (float*)HT;                     // [4][32][64] gate partials (ALIAS)
    float*  CST = (float*)(HT + 32 * HSTRH);      // [512]
    float*  HST = CST + 512;                      // [512]
    int*    NBT = (int*)(HST + 512);              // [T_]
    int*    SLEN = NBT + T_;                      // [32] sorted lengths
    int*    SPRM = SLEN + 32;                     // [32] sorted -> orig batch

    const int tid = threadIdx.x, warp = tid >> 5, lane = tid & 31;
    const int cta = blockIdx.x;
    const int dir = cta >> 6;
    const int j0  = (cta & 63) * 16;
    const float*  xp   = dir ? xpB : xpF;
    const __half* Wh   = dir ? WhB : WhF;
    __half*       hdir = dir ? hB : hF;

    unsigned epoch = g_bgen[dir * 32];

    for (int p = tid; p < 512; p += 256) {
        int b = p >> 4, jl = p & 15;
        CST[p] = 0.f; HST[p] = 0.f;
        hdir[b * H_ + j0 + jl] = __float2half(0.f);
    }
    if (tid < 32) {
        int pb = g_perm[tid];
        SPRM[tid] = pb;
        SLEN[tid] = lengths[pb];
    }
    for (int i = tid; i < T_; i += 256) NBT[i] = g_nbt[i];
    const int Tmax = g_Tmax;
#pragma unroll
    for (int i = 0; i < 32; i++) {
        int seg = tid + i * 256;
        int r = seg >> 7, c8 = (seg & 127) * 8;
        cp16(WH + r * HSTRH + c8,
             Wh + ((size_t)((r >> 4) * H_ + j0 + (r & 15))) * H_ + c8);
    }
    cp_commit(); cp_wait<0>();
    __syncthreads();

    const uint32_t HTu = s2u(HT);
    const uint32_t WHu = s2u(WH);
    const int kq  = warp >> 1;                    // k-quarter (0..3)
    const int nh  = warp & 1;                     // n-half (0/1)
    const int kb  = kq * 256;                     // k base (halves)
    const int rpA = (lane & 7) + ((lane >> 3) & 1) * 8;
    const int kpA = (lane >> 4) * 8;
    const uint32_t aB0 = HTu + ((0  + rpA) * HSTRH + kpA + kb) * 2;
    const uint32_t aB1 = HTu + ((16 + rpA) * HSTRH + kpA + kb) * 2;
    const int rpB = nh * 32 + (lane & 7) + (lane >> 4) * 8;
    const int kpB = ((lane >> 3) & 1) * 8;
    const uint32_t bB0 = WHu + (rpB * HSTRH + kpB + kb) * 2;
    const uint32_t bB1 = bB0 + 16 * HSTRH * 2;
    float* GSw = GSB + kq * 32 * 64;

    // hoist this warp's W fragments into registers (n32 x k256 tile)
    uint32_t BF[16][8];
#pragma unroll
    for (int ks = 0; ks < 16; ks++) {
        ldsm4(BF[ks],     bB0 + ks * 32);
        ldsm4(BF[ks] + 4, bB1 + ks * 32);
    }
    grid_barrier(dir, ++epoch);

    auto issueHC = [&](int colbase, int nrow8) {
        for (int i = 0; i < nrow8; i++) {
            int seg = tid + i * 256;
            int row = seg >> 5, c8 = (seg & 31) * 8;
            cp16(HT + row * HSTRH + colbase + c8, hdir + row * H_ + colbase + c8);
        }
    };

    auto prefetchXP = [&](int t, float xr[2][4], bool act[2]) {
#pragma unroll
        for (int p2 = 0; p2 < 2; p2++) {
            int p = tid + p2 * 256, b = p >> 4, jl = p & 15;
            act[p2] = (t < SLEN[b]);
            if (act[p2]) {
                int pb = SPRM[b];
                int teff = dir ? (SLEN[b] - 1 - t) : t;
                const float* xb = xp + ((size_t)(pb * T_ + teff)) * G4_ + j0 + jl;
                xr[p2][0] = __ldcs(xb);
                xr[p2][1] = __ldcs(xb + H_);
                xr[p2][2] = __ldcs(xb + 2 * H_);
                xr[p2][3] = __ldcs(xb + 3 * H_);
            }
        }
    };

    float xr[2][4];  bool act[2];
    float xrn[2][4]; bool actn[2];
    prefetchXP(0, xr, act);

    __half outh[2];
    int    outix[2];
    bool   outa[2] = { false, false };

    for (int t = 0; t < Tmax; t++) {
        const int nb = NBT[t];
        const bool full = nb > 16;
        const int nrow8 = full ? 4 : 2;

        // issue h chunks in k order (quarter q consumes chunk q)
        issueHC(0,   nrow8); cp_commit();
        issueHC(256, nrow8); cp_commit();
        issueHC(512, nrow8); cp_commit();
        issueHC(768, nrow8); cp_commit();

        // deferred out writes from step t-1 (overlap h load)
        if (out) {
#pragma unroll
            for (int p2 = 0; p2 < 2; p2++)
                if (outa[p2]) out[outix[p2]] = outh[p2];
        }
        // prefetch next step's xp (overlaps MMA below)
        if (t + 1 < Tmax) prefetchXP(t + 1, xrn, actn);

        float acc[2][4][4];
#pragma unroll
        for (int a = 0; a < 2; a++)
#pragma unroll
            for (int b = 0; b < 4; b++)
#pragma unroll
                for (int k = 0; k < 4; k++) acc[a][b][k] = 0.f;

        // phase A: chunks 0,1 resident -> quarters 0,1 compute
        cp_wait<2>();
        __syncthreads();
        if (kq < 2) {
#pragma unroll
            for (int ks = 0; ks < 16; ks++) {
                uint32_t a0[4];
                ldsm4(a0, aB0 + ks * 32);
                mma16(acc[0][0], a0, BF[ks]);
                mma16(acc[0][1], a0, BF[ks] + 2);
                mma16(acc[0][2], a0, BF[ks] + 4);
                mma16(acc[0][3], a0, BF[ks] + 6);
                if (full) {
                    uint32_t a1[4];
                    ldsm4(a1, aB1 + ks * 32);
                    mma16(acc[1][0], a1, BF[ks]);
                    mma16(acc[1][1], a1, BF[ks] + 2);
                    mma16(acc[1][2], a1, BF[ks] + 4);
                    mma16(acc[1][3], a1, BF[ks] + 6);
                }
            }
        }

        // phase B: chunks 2,3 resident -> quarters 2,3 compute
        cp_wait<0>();
        __syncthreads();
        if (kq >= 2) {
#pragma unroll
            for (int ks = 0; ks < 16; ks++) {
                uint32_t a0[4];
                ldsm4(a0, aB0 + ks * 32);
                mma16(acc[0][0], a0, BF[ks]);
                mma16(acc[0][1], a0, BF[ks] + 2);
                mma16(acc[0][2], a0, BF[ks] + 4);
                mma16(acc[0][3], a0, BF[ks] + 6);
                if (full) {
                    uint32_t a1[4];
                    ldsm4(a1, aB1 + ks * 32);
                    mma16(acc[1][0], a1, BF[ks]);
                    mma16(acc[1][1], a1, BF[ks] + 2);
                    mma16(acc[1][2], a1, BF[ks] + 4);
                    mma16(acc[1][3], a1, BF[ks] + 6);
                }
            }
        }
        __syncthreads();     // all HT ldsm done before GS alias writes

        // dump gate partials: warp owns cols [nh*32, nh*32+32) of GSB[kq]
        {
            int rowb = lane >> 2, colb = nh * 32 + 2 * (lane & 3);
#pragma unroll
            for (int nt = 0; nt < 4; nt++) {
                GSw[rowb * 64 + colb + nt * 8]           = acc[0][nt][0];
                GSw[rowb * 64 + colb + nt * 8 + 1]       = acc[0][nt][1];
                GSw[(rowb + 8) * 64 + colb + nt * 8]     = acc[0][nt][2];
                GSw[(rowb + 8) * 64 + colb + nt * 8 + 1] = acc[0][nt][3];
            }
            if (full) {
#pragma unroll
                for (int nt = 0; nt < 4; nt++) {
                    GSw[(16 + rowb) * 64 + colb + nt * 8]     = acc[1][nt][0];
                    GSw[(16 + rowb) * 64 + colb + nt * 8 + 1] = acc[1][nt][1];
                    GSw[(24 + rowb) * 64 + colb + nt * 8]     = acc[1][nt][2];
                    GSw[(24 + rowb) * 64 + colb + nt * 8 + 1] = acc[1][nt][3];
                }
            }
        }
        __syncthreads();

        // LSTM cell (live rows only); sum the 4 k-quarter partials
#pragma unroll
        for (int p2 = 0; p2 < 2; p2++) {
            if (!act[p2]) { outa[p2] = false; continue; }
            int p = tid + p2 * 256, b = p >> 4, jl = p & 15;
            float gi = xr[p2][0], gf = xr[p2][1], gg = xr[p2][2], go = xr[p2][3];
#pragma unroll
            for (int q = 0; q < 4; q++) {
                const float* G = GSB + q * 32 * 64 + b * 64;
                gi += G[jl];
                gf += G[16 + jl];
                gg += G[32 + jl];
                go += G[48 + jl];
            }
            float ii = sigmoidf_(gi), ff = sigmoidf_(gf);
            float gv = tanhf(gg),     oo = sigmoidf_(go);
            float cn = ff * CST[p] + ii * gv;
            float hn = oo * tanhf(cn);
            CST[p] = cn; HST[p] = hn;
            __half hh = __float2half_rn(hn);
            hdir[b * H_ + j0 + jl] = hh;
            if (out) {
                int pb = SPRM[b];
                int pout = dir ? (SLEN[b] - 1 - t) : t;
                outh[p2] = hh;
                outix[p2] = (pb * T_ + pout) * (2 * H_) + dir * H_ + j0 + jl;
                outa[p2] = true;
            }
        }
        grid_barrier(dir, ++epoch);

#pragma unroll
        for (int p2 = 0; p2 < 2; p2++) {
            act[p2] = actn[p2];
#pragma unroll
            for (int q = 0; q < 4; q++) xr[p2][q] = xrn[p2][q];
        }
    }
    if (out) {
#pragma unroll
        for (int p2 = 0; p2 < 2; p2++)
            if (outa[p2]) out[outix[p2]] = outh[p2];
    }
}

// ---------------- kernel 4: final linear  out = [h2b, h2f] @ lin_w^T + b ---
__global__ __launch_bounds__(256) void final_linear_kernel(
    const __half* __restrict__ hF, const __half* __restrict__ hB,
    const float* __restrict__ lw, const float* __restrict__ lb,
    float* __restrict__ outp)
{
    int w = (blockIdx.x * blockDim.x + threadIdx.x) >> 5;
    int lane = threadIdx.x & 31;
    if (w >= B_ * 2) return;
    int b = w >> 1, c = w & 1;
    int pb = g_perm[b];
    float s = 0.f;
    for (int k = lane; k < 2 * H_; k += 32) {
        float xv = __half2float((k < H_) ? hB[b * H_ + k] : hF[b * H_ + (k - H_)]);
        s += xv * lw[c * 2 * H_ + k];
    }
#pragma unroll
    for (int o = 16; o; o >>= 1) s += __shfl_xor_sync(0xffffffffu, s, o);
    if (lane == 0) outp[pb * 2 + c] = s + lb[c];
}

// ---------------- launch ----------------------------------------------------
extern "C" void kernel_launch(void* const* d_in, const int* in_sizes, int n_in,
                              void* d_out, int out_size)
{
    const int*   tok      = (const int*)  d_in[0];
    const int*   lens     = (const int*)  d_in[1];
    const float* emb      = (const float*)d_in[2];
    const float* w_ih_l0f = (const float*)d_in[3];
    const float* w_hh_l0f = (const float*)d_in[4];
    const float* b_ih_l0f = (const float*)d_in[5];
    const float* b_hh_l0f = (const float*)d_in[6];
    const float* w_ih_l0b = (const float*)d_in[7];
    const float* w_hh_l0b = (const float*)d_in[8];
    const float* b_ih_l0b = (const float*)d_in[9];
    const float* b_hh_l0b = (const float*)d_in[10];
    const float* w_ih_l1f = (const float*)d_in[11];
    const float* w_hh_l1f = (const float*)d_in[12];
    const float* b_ih_l1f = (const float*)d_in[13];
    const float* b_hh_l1f = (const float*)d_in[14];
    const float* w_ih_l1b = (const float*)d_in[15];
    const float* w_hh_l1b = (const float*)d_in[16];
    const float* b_ih_l1b = (const float*)d_in[17];
    const float* b_hh_l1b = (const float*)d_in[18];
    const float* lin_w    = (const float*)d_in[19];
    const float* lin_b    = (const float*)d_in[20];

    __half *x, *wA, *wB, *whF, *whB, *out0, *hF, *hB;
    float *xpF, *xpB;
    cudaGetSymbolAddress((void**)&x,    g_x);
    cudaGetSymbolAddress((void**)&wA,   g_wA);
    cudaGetSymbolAddress((void**)&wB,   g_wB);
    cudaGetSymbolAddress((void**)&whF,  g_whF);
    cudaGetSymbolAddress((void**)&whB,  g_whB);
    cudaGetSymbolAddress((void**)&xpF,  g_xpF);
    cudaGetSymbolAddress((void**)&xpB,  g_xpB);
    cudaGetSymbolAddress((void**)&out0, g_out0);
    cudaGetSymbolAddress((void**)&hF,   g_hF);
    cudaGetSymbolAddress((void**)&hB,   g_hB);

    cudaFuncSetAttribute(gemm_f16, cudaFuncAttributeMaxDynamicSharedMemorySize, GEMM_SMEM);
    cudaFuncSetAttribute(lstm_layer_kernel, cudaFuncAttributeMaxDynamicSharedMemorySize, LSTM_SMEM);

    dim3 gg(G4_ / 128, M_ / 128);

    // compacted row index + sorted perm + nbt
    build_idx_kernel<<<1, 256>>>(lens);

    // embedding gather -> fp16, K padded to 320
    gather_kernel<<<(M_ * EP_ + 255) / 256, 256>>>(tok, emb, x);

    // layer-0 weight conversions, then input projections (Ka = 320)
    conv_f16_pad300<<<(G4_ * 80 + 255) / 256, 256>>>((const float4*)w_ih_l0f, (__half2*)wA, G4_);
    conv_f16_pad300<<<(G4_ * 80 + 255) / 256, 256>>>((const float4*)w_ih_l0b, (__half2*)wB, G4_);
    conv_f16_v4<<<(G4_ * H_ / 4 + 255) / 256, 256>>>((const float4*)w_hh_l0f, (__half2*)whF, G4_ * H_ / 4);
    conv_f16_v4<<<(G4_ * H_ / 4 + 255) / 256, 256>>>((const float4*)w_hh_l0b, (__half2*)whB, G4_ * H_ / 4);
    gemm_f16<<<gg, 256, GEMM_SMEM>>>(x, wA, b_ih_l0f, b_hh_l0f, xpF, EP_);
    gemm_f16<<<gg, 256, GEMM_SMEM>>>(x, wB, b_ih_l0b, b_hh_l0b, xpB, EP_);

    // layer-0 recurrence (writes [out_f || out_b] as fp16)
    lstm_layer_kernel<<<NCTA_REC, 256, LSTM_SMEM>>>(xpF, xpB, whF, whB, lens,
                                                    out0, hF, hB);

    // layer-1 weight conversions, then input projections (Ka = 2048)
    conv_f16_v4<<<(G4_ * 2048 / 4 + 255) / 256, 256>>>((const float4*)w_ih_l1f, (__half2*)wA, G4_ * 2048 / 4);
    conv_f16_v4<<<(G4_ * 2048 / 4 + 255) / 256, 256>>>((const float4*)w_ih_l1b, (__half2*)wB, G4_ * 2048 / 4);
    conv_f16_v4<<<(G4_ * H_ / 4 + 255) / 256, 256>>>((const float4*)w_hh_l1f, (__half2*)whF, G4_ * H_ / 4);
    conv_f16_v4<<<(G4_ * H_ / 4 + 255) / 256, 256>>>((const float4*)w_hh_l1b, (__half2*)whB, G4_ * H_ / 4);
    gemm_f16<<<gg, 256, GEMM_SMEM>>>(out0, wA, b_ih_l1f, b_hh_l1f, xpF, 2 * H_);
    gemm_f16<<<gg, 256, GEMM_SMEM>>>(out0, wB, b_ih_l1b, b_hh_l1b, xpB, 2 * H_);

    // layer-1 recurrence (only final hiddens needed)
    lstm_layer_kernel<<<NCTA_REC, 256, LSTM_SMEM>>>(xpF, xpB, whF, whB, lens,
                                                    (__half*)nullptr, hF, hB);

    // head
    final_linear_kernel<<<8, 256>>>(hF, hB, lin_w, lin_b, (float*)d_out);
}